// round 1
// baseline (speedup 1.0000x reference)
#include <cuda_runtime.h>
#include <cstdint>

#define INV_T   (1.0f/0.07f)
#define N_ROWS  512
#define D_IN    2048
#define DIM     128
#define KNEG    65536
#define NG      4
#define CH      8
#define QS_LD   130

// persistent device scratch (no allocations allowed)
__device__ float g_part[8 * N_ROWS * DIM];   // [2 mats][4 ksplit][512][128]
__device__ float g_q[N_ROWS * DIM];          // normalized q, pre-scaled by 1/T
__device__ int   g_rows[NG * N_ROWS];
__device__ int   g_cnt[NG];

// ---------------------------------------------------------------- init
__global__ void init_kernel(float* __restrict__ out, long long out_size) {
    int t = threadIdx.x;
    if (t < NG) g_cnt[t] = 0;
    long long base = (long long)N_ROWS * (KNEG + 1);
    for (long long i = base + t; i < out_size; i += blockDim.x)
        out[i] = 0.0f;   // labels tail (zeros) if present
}

// ---------------------------------------------------------------- projections (split-K partials)
__global__ void __launch_bounds__(256) proj_kernel(
    const float* __restrict__ im_q, const float* __restrict__ im_k,
    const float* __restrict__ W_q,  const float* __restrict__ W_k) {
    const int z  = blockIdx.z;          // 0 = q, 1 = k
    const int ks = blockIdx.y;          // K split 0..3 (512 each)
    const int n0 = blockIdx.x * 16;
    const float* __restrict__ A = z ? im_k : im_q;
    const float* __restrict__ W = z ? W_k  : W_q;

    __shared__ float As[16][32];
    __shared__ float Bs[32][128];

    float acc[2][4] = {{0.f,0.f,0.f,0.f},{0.f,0.f,0.f,0.f}};
    const int t  = threadIdx.x;
    const int r0 = (t >> 5) << 1;       // 0..14
    const int c0 = (t & 31) << 2;       // 0..124
    const int kbeg = ks * 512;

    for (int kb = 0; kb < 512; kb += 32) {
        const int kbase = kbeg + kb;
        {
            int idx = t;
            #pragma unroll
            for (int i = 0; i < 2; ++i) {
                int r = idx >> 5, c = idx & 31;
                As[r][c] = A[(size_t)(n0 + r) * D_IN + kbase + c];
                idx += 256;
            }
        }
        #pragma unroll
        for (int i = 0; i < 16; ++i) {
            int idx = t + i * 256;
            int r = idx >> 7, c = idx & 127;
            Bs[r][c] = W[(size_t)(kbase + r) * DIM + c];
        }
        __syncthreads();
        #pragma unroll
        for (int kc = 0; kc < 32; ++kc) {
            float a0 = As[r0][kc], a1 = As[r0 + 1][kc];
            float4 b = *(const float4*)&Bs[kc][c0];
            acc[0][0] += a0 * b.x; acc[0][1] += a0 * b.y;
            acc[0][2] += a0 * b.z; acc[0][3] += a0 * b.w;
            acc[1][0] += a1 * b.x; acc[1][1] += a1 * b.y;
            acc[1][2] += a1 * b.z; acc[1][3] += a1 * b.w;
        }
        __syncthreads();
    }
    float* P = g_part + ((size_t)(z * 4 + ks) * N_ROWS + n0) * DIM;
    #pragma unroll
    for (int rr = 0; rr < 2; ++rr)
        #pragma unroll
        for (int cc = 0; cc < 4; ++cc)
            P[(size_t)(r0 + rr) * DIM + c0 + cc] = acc[rr][cc];
}

// ---------------------------------------------------------------- norm + l_pos + routing
__device__ __forceinline__ float block_reduce_128(float v, volatile float* sbuf) {
    #pragma unroll
    for (int o = 16; o > 0; o >>= 1)
        v += __shfl_xor_sync(0xffffffffu, v, o);
    __syncthreads();
    if ((threadIdx.x & 31) == 0) sbuf[threadIdx.x >> 5] = v;
    __syncthreads();
    return sbuf[0] + sbuf[1] + sbuf[2] + sbuf[3];
}

__global__ void __launch_bounds__(128) norm_kernel(const int* __restrict__ label,
                                                   float* __restrict__ out) {
    const int n = blockIdx.x;
    const int j = threadIdx.x;
    __shared__ float sbuf[4];

    float qv = 0.f, kv = 0.f;
    #pragma unroll
    for (int s = 0; s < 4; ++s) {
        qv += g_part[((size_t)s       * N_ROWS + n) * DIM + j];
        kv += g_part[((size_t)(4 + s) * N_ROWS + n) * DIM + j];
    }
    float sq = block_reduce_128(qv * qv, sbuf);
    float sk = block_reduce_128(kv * kv, sbuf);
    float qn = qv / fmaxf(sqrtf(sq), 1e-12f);
    float kn = kv / fmaxf(sqrtf(sk), 1e-12f);
    float lp = block_reduce_128(qn * kn, sbuf);

    g_q[(size_t)n * DIM + j] = qn * INV_T;   // pre-scaled by 1/T for l_neg

    if (j == 0) {
        out[(size_t)n * (KNEG + 1)] = lp * INV_T;
        int lab = label[n];
        int gq = ((lab - 1) % NG + NG) % NG;
        int p = atomicAdd(&g_cnt[gq], 1);
        g_rows[gq * N_ROWS + p] = n;
    }
}

// ---------------------------------------------------------------- l_neg grouped GEMM (f32x2)
__device__ __forceinline__ unsigned long long dup2(float v) {
    unsigned long long r;
    asm("mov.b64 %0, {%1, %1};" : "=l"(r) : "f"(v));
    return r;
}
__device__ __forceinline__ void ffma2(unsigned long long& d,
                                      unsigned long long a, unsigned long long b) {
    asm("fma.rn.f32x2 %0, %1, %2, %0;" : "+l"(d) : "l"(a), "l"(b));
}
__device__ __forceinline__ float2 unpk(unsigned long long v) {
    float2 r;
    asm("mov.b64 {%0, %1}, %2;" : "=f"(r.x), "=f"(r.y) : "l"(v));
    return r;
}

__global__ void __launch_bounds__(256) lneg_kernel(const float* __restrict__ queues,
                                                   float* __restrict__ out) {
    const int g  = blockIdx.y;
    const int m0 = blockIdx.z * 128;
    const int cnt = g_cnt[g];
    if (m0 >= cnt) return;                 // uniform exit
    const int k0 = blockIdx.x * 128;

    extern __shared__ float smem[];
    float* qs   = smem;                              // [DIM][QS_LD] transposed q tile
    float* ques = smem + DIM * QS_LD;                // [2][CH][128]
    int*  rowidx = (int*)(ques + 2 * CH * 128);      // [128]

    const int t = threadIdx.x;
    if (t < 128) {
        int r = m0 + t;
        rowidx[t] = (r < cnt) ? g_rows[g * N_ROWS + r] : -1;
    }

    const float* qbase = queues + (size_t)g * DIM * KNEG + k0;
    unsigned ques_sh = (unsigned)__cvta_generic_to_shared(ques);

    // prefetch queue chunk 0 (buf 0)
    {
        int c   = t >> 5;
        int seg = (t & 31) << 2;
        const float* src = qbase + (size_t)c * KNEG + seg;
        unsigned dst = ques_sh + (unsigned)((c * 128 + seg) * 4);
        asm volatile("cp.async.cg.shared.global [%0], [%1], 16;" :: "r"(dst), "l"(src));
        asm volatile("cp.async.commit_group;");
    }

    __syncthreads();   // rowidx visible

    // q tile [128 rows][128 c] -> qs[c][r] (padded for bank-safe 64b pair loads)
    #pragma unroll
    for (int i = 0; i < 16; ++i) {
        int idx = t + (i << 8);
        int r  = idx >> 5;
        int c4 = (idx & 31) << 2;
        int n = rowidx[r]; if (n < 0) n = 0;   // safe addr; value never stored
        float4 v = *(const float4*)&g_q[(size_t)n * DIM + c4];
        qs[(c4 + 0) * QS_LD + r] = v.x;
        qs[(c4 + 1) * QS_LD + r] = v.y;
        qs[(c4 + 2) * QS_LD + r] = v.z;
        qs[(c4 + 3) * QS_LD + r] = v.w;
    }

    unsigned long long acc[4][8];
    #pragma unroll
    for (int i = 0; i < 4; ++i)
        #pragma unroll
        for (int j = 0; j < 8; ++j) acc[i][j] = 0ULL;

    const int r0  = (t >> 4) << 3;   // 8 rows  (4 row-pairs)
    const int kc0 = (t & 15) << 3;   // 8 cols

    int buf = 0;
    for (int ch = 0; ch < 16; ++ch) {
        if (ch < 15) {
            int c   = t >> 5;
            int seg = (t & 31) << 2;
            const float* src = qbase + (size_t)((ch + 1) * CH + c) * KNEG + seg;
            unsigned dst = ques_sh + (unsigned)((((buf ^ 1) * CH + c) * 128 + seg) * 4);
            asm volatile("cp.async.cg.shared.global [%0], [%1], 16;" :: "r"(dst), "l"(src));
            asm volatile("cp.async.commit_group;");
            asm volatile("cp.async.wait_group 1;");
        } else {
            asm volatile("cp.async.wait_group 0;");
        }
        __syncthreads();

        #pragma unroll
        for (int c = 0; c < CH; ++c) {
            const int cabs = ch * CH + c;
            const float* qcol = qs + cabs * QS_LD + r0;
            unsigned long long qp[4];
            qp[0] = *(const unsigned long long*)(qcol + 0);
            qp[1] = *(const unsigned long long*)(qcol + 2);
            qp[2] = *(const unsigned long long*)(qcol + 4);
            qp[3] = *(const unsigned long long*)(qcol + 6);
            const float* qrow = ques + (buf * CH + c) * 128 + kc0;
            float4 v0 = *(const float4*)(qrow);
            float4 v1 = *(const float4*)(qrow + 4);
            unsigned long long b[8];
            b[0] = dup2(v0.x); b[1] = dup2(v0.y); b[2] = dup2(v0.z); b[3] = dup2(v0.w);
            b[4] = dup2(v1.x); b[5] = dup2(v1.y); b[6] = dup2(v1.z); b[7] = dup2(v1.w);
            #pragma unroll
            for (int i = 0; i < 4; ++i)
                #pragma unroll
                for (int j = 0; j < 8; ++j)
                    ffma2(acc[i][j], qp[i], b[j]);
        }
        __syncthreads();
        buf ^= 1;
    }

    // epilogue: scatter rows (q pre-scaled by 1/T, so no extra scaling)
    #pragma unroll
    for (int i = 0; i < 4; ++i) {
        int rA = r0 + 2 * i, rB = rA + 1;
        int nA = rowidx[rA], nB = rowidx[rB];
        #pragma unroll
        for (int j = 0; j < 8; ++j) {
            float2 f = unpk(acc[i][j]);
            size_t col = (size_t)(1 + k0 + kc0 + j);
            if (nA >= 0) out[(size_t)nA * (KNEG + 1) + col] = f.x;
            if (nB >= 0) out[(size_t)nB * (KNEG + 1) + col] = f.y;
        }
    }
}

// ---------------------------------------------------------------- launch
extern "C" void kernel_launch(void* const* d_in, const int* in_sizes, int n_in,
                              void* d_out, int out_size) {
    const float* im_q   = (const float*)d_in[0];
    const float* im_k   = (const float*)d_in[1];
    const float* W_q    = (const float*)d_in[2];
    const float* W_k    = (const float*)d_in[3];
    const float* queues = (const float*)d_in[4];
    const int*   label  = (const int*)d_in[5];
    float* out = (float*)d_out;

    const int smem3 = (DIM * QS_LD + 2 * CH * 128) * 4 + 128 * 4;
    cudaFuncSetAttribute(lneg_kernel, cudaFuncAttributeMaxDynamicSharedMemorySize, smem3);

    init_kernel<<<1, 256>>>(out, (long long)out_size);
    proj_kernel<<<dim3(32, 4, 2), 256>>>(im_q, im_k, W_q, W_k);
    norm_kernel<<<N_ROWS, 128>>>(label, out);
    lneg_kernel<<<dim3(KNEG / 128, NG, 4), 256, smem3>>>(queues, out);
}

// round 2
// speedup vs baseline: 1.2316x; 1.2316x over previous
#include <cuda_runtime.h>
#include <cstdint>

#define INV_T   (1.0f/0.07f)
#define N_ROWS  512
#define D_IN    2048
#define DIM     128
#define KNEG    65536
#define NG      4
#define CH      16
#define QS_LD   132

// persistent device scratch (no allocations allowed)
__device__ float g_part[8 * N_ROWS * DIM];   // [2 mats][4 ksplit][512][128]
__device__ float g_q[N_ROWS * DIM];          // normalized q, pre-scaled by 1/T
__device__ int   g_rows[NG * N_ROWS];
__device__ int   g_cnt[NG];

// ---------------------------------------------------------------- init
__global__ void init_kernel(float* __restrict__ out, long long out_size) {
    int t = threadIdx.x;
    if (t < NG) g_cnt[t] = 0;
    long long base = (long long)N_ROWS * (KNEG + 1);
    for (long long i = base + t; i < out_size; i += blockDim.x)
        out[i] = 0.0f;   // labels tail (zeros) if present
}

// ---------------------------------------------------------------- projections (split-K partials)
__global__ void __launch_bounds__(256) proj_kernel(
    const float* __restrict__ im_q, const float* __restrict__ im_k,
    const float* __restrict__ W_q,  const float* __restrict__ W_k) {
    const int z  = blockIdx.z;          // 0 = q, 1 = k
    const int ks = blockIdx.y;          // K split 0..3 (512 each)
    const int n0 = blockIdx.x * 16;
    const float* __restrict__ A = z ? im_k : im_q;
    const float* __restrict__ W = z ? W_k  : W_q;

    __shared__ float As[16][32];
    __shared__ float Bs[32][128];

    float acc[2][4] = {{0.f,0.f,0.f,0.f},{0.f,0.f,0.f,0.f}};
    const int t  = threadIdx.x;
    const int r0 = (t >> 5) << 1;       // 0..14
    const int c0 = (t & 31) << 2;       // 0..124
    const int kbeg = ks * 512;

    for (int kb = 0; kb < 512; kb += 32) {
        const int kbase = kbeg + kb;
        {
            int idx = t;
            #pragma unroll
            for (int i = 0; i < 2; ++i) {
                int r = idx >> 5, c = idx & 31;
                As[r][c] = A[(size_t)(n0 + r) * D_IN + kbase + c];
                idx += 256;
            }
        }
        #pragma unroll
        for (int i = 0; i < 16; ++i) {
            int idx = t + i * 256;
            int r = idx >> 7, c = idx & 127;
            Bs[r][c] = W[(size_t)(kbase + r) * DIM + c];
        }
        __syncthreads();
        #pragma unroll
        for (int kc = 0; kc < 32; ++kc) {
            float a0 = As[r0][kc], a1 = As[r0 + 1][kc];
            float4 b = *(const float4*)&Bs[kc][c0];
            acc[0][0] += a0 * b.x; acc[0][1] += a0 * b.y;
            acc[0][2] += a0 * b.z; acc[0][3] += a0 * b.w;
            acc[1][0] += a1 * b.x; acc[1][1] += a1 * b.y;
            acc[1][2] += a1 * b.z; acc[1][3] += a1 * b.w;
        }
        __syncthreads();
    }
    float* P = g_part + ((size_t)(z * 4 + ks) * N_ROWS + n0) * DIM;
    #pragma unroll
    for (int rr = 0; rr < 2; ++rr)
        #pragma unroll
        for (int cc = 0; cc < 4; ++cc)
            P[(size_t)(r0 + rr) * DIM + c0 + cc] = acc[rr][cc];
}

// ---------------------------------------------------------------- norm + l_pos + routing
__device__ __forceinline__ float block_reduce_128(float v, volatile float* sbuf) {
    #pragma unroll
    for (int o = 16; o > 0; o >>= 1)
        v += __shfl_xor_sync(0xffffffffu, v, o);
    __syncthreads();
    if ((threadIdx.x & 31) == 0) sbuf[threadIdx.x >> 5] = v;
    __syncthreads();
    return sbuf[0] + sbuf[1] + sbuf[2] + sbuf[3];
}

__global__ void __launch_bounds__(128) norm_kernel(const int* __restrict__ label,
                                                   float* __restrict__ out) {
    const int n = blockIdx.x;
    const int j = threadIdx.x;
    __shared__ float sbuf[4];

    float qv = 0.f, kv = 0.f;
    #pragma unroll
    for (int s = 0; s < 4; ++s) {
        qv += g_part[((size_t)s       * N_ROWS + n) * DIM + j];
        kv += g_part[((size_t)(4 + s) * N_ROWS + n) * DIM + j];
    }
    float sq = block_reduce_128(qv * qv, sbuf);
    float sk = block_reduce_128(kv * kv, sbuf);
    float qn = qv / fmaxf(sqrtf(sq), 1e-12f);
    float kn = kv / fmaxf(sqrtf(sk), 1e-12f);
    float lp = block_reduce_128(qn * kn, sbuf);

    g_q[(size_t)n * DIM + j] = qn * INV_T;   // pre-scaled by 1/T for l_neg

    if (j == 0) {
        out[(size_t)n * (KNEG + 1)] = lp * INV_T;
        int lab = label[n];
        int gq = ((lab - 1) % NG + NG) % NG;
        int p = atomicAdd(&g_cnt[gq], 1);
        g_rows[gq * N_ROWS + p] = n;
    }
}

// ---------------------------------------------------------------- l_neg grouped GEMM (f32x2)
__device__ __forceinline__ unsigned long long dup2(float v) {
    unsigned long long r;
    asm("mov.b64 %0, {%1, %1};" : "=l"(r) : "f"(v));
    return r;
}
__device__ __forceinline__ void ffma2(unsigned long long& d,
                                      unsigned long long a, unsigned long long b) {
    asm("fma.rn.f32x2 %0, %1, %2, %0;" : "+l"(d) : "l"(a), "l"(b));
}
__device__ __forceinline__ float2 unpk(unsigned long long v) {
    float2 r;
    asm("mov.b64 {%0, %1}, %2;" : "=f"(r.x), "=f"(r.y) : "l"(v));
    return r;
}

__global__ void __launch_bounds__(256, 2) lneg_kernel(const float* __restrict__ queues,
                                                      float* __restrict__ out) {
    const int g  = blockIdx.y;
    const int m0 = blockIdx.z * 128;
    const int cnt = g_cnt[g];
    if (m0 >= cnt) return;                 // uniform exit
    const int k0 = blockIdx.x * 128;

    extern __shared__ float smem[];
    float* qs   = smem;                              // [DIM][QS_LD] transposed q tile
    float* ques = smem + DIM * QS_LD;                // [2][CH][128]
    int*  rowidx = (int*)(ques + 2 * CH * 128);      // [128]

    const int t = threadIdx.x;
    if (t < 128) {
        int r = m0 + t;
        rowidx[t] = (r < cnt) ? g_rows[g * N_ROWS + r] : -1;
    }

    const float* qbase = queues + (size_t)g * DIM * KNEG + k0;
    unsigned ques_sh = (unsigned)__cvta_generic_to_shared(ques);

    // prefetch queue chunk 0 (buf 0): 16 features x 128 k = 8KB, 2 x 16B per thread
    #pragma unroll
    for (int h = 0; h < 2; ++h) {
        int s  = t + h * 256;
        int c  = s >> 5;                 // 0..15
        int sg = (s & 31) << 2;          // float offset 0..124
        const float* src = qbase + (size_t)c * KNEG + sg;
        unsigned dst = ques_sh + (unsigned)((c * 128 + sg) * 4);
        asm volatile("cp.async.cg.shared.global [%0], [%1], 16;" :: "r"(dst), "l"(src));
    }
    asm volatile("cp.async.commit_group;");

    __syncthreads();   // rowidx visible

    // q tile [128 rows][128 c] -> qs[c][r] (QS_LD=132: 16B-aligned column pairs)
    #pragma unroll
    for (int i = 0; i < 16; ++i) {
        int idx = t + (i << 8);
        int r  = idx >> 5;
        int c4 = (idx & 31) << 2;
        int n = rowidx[r]; if (n < 0) n = 0;   // safe addr; value never stored
        float4 v = *(const float4*)&g_q[(size_t)n * DIM + c4];
        qs[(c4 + 0) * QS_LD + r] = v.x;
        qs[(c4 + 1) * QS_LD + r] = v.y;
        qs[(c4 + 2) * QS_LD + r] = v.z;
        qs[(c4 + 3) * QS_LD + r] = v.w;
    }

    unsigned long long acc[4][8];
    #pragma unroll
    for (int i = 0; i < 4; ++i)
        #pragma unroll
        for (int j = 0; j < 8; ++j) acc[i][j] = 0ULL;

    const int r0 = (t >> 4) << 3;    // 8 rows (4 row-pairs)
    const int c4 = (t & 15) << 2;    // cols c4..c4+3 and c4+64..c4+67

    int buf = 0;
    for (int ch = 0; ch < DIM / CH; ++ch) {
        if (ch < DIM / CH - 1) {
            #pragma unroll
            for (int h = 0; h < 2; ++h) {
                int s  = t + h * 256;
                int c  = s >> 5;
                int sg = (s & 31) << 2;
                const float* src = qbase + (size_t)((ch + 1) * CH + c) * KNEG + sg;
                unsigned dst = ques_sh + (unsigned)((((buf ^ 1) * CH + c) * 128 + sg) * 4);
                asm volatile("cp.async.cg.shared.global [%0], [%1], 16;" :: "r"(dst), "l"(src));
            }
            asm volatile("cp.async.commit_group;");
            asm volatile("cp.async.wait_group 1;");
        } else {
            asm volatile("cp.async.wait_group 0;");
        }
        __syncthreads();

        const float* qcol0 = qs + (ch * CH) * QS_LD + r0;
        const float* brow0 = ques + (buf * CH) * 128;

        // software-pipelined inner loop over CH features
        ulonglong2 qpA = *(const ulonglong2*)(qcol0);
        ulonglong2 qpB = *(const ulonglong2*)(qcol0 + 4);
        float4 bA = *(const float4*)(brow0 + c4);
        float4 bB = *(const float4*)(brow0 + c4 + 64);

        #pragma unroll
        for (int c = 0; c < CH; ++c) {
            ulonglong2 nqA, nqB; float4 nbA, nbB;
            if (c + 1 < CH) {
                const float* qn = qcol0 + (c + 1) * QS_LD;
                nqA = *(const ulonglong2*)(qn);
                nqB = *(const ulonglong2*)(qn + 4);
                const float* bn = brow0 + (c + 1) * 128;
                nbA = *(const float4*)(bn + c4);
                nbB = *(const float4*)(bn + c4 + 64);
            }
            unsigned long long b[8];
            b[0] = dup2(bA.x); b[1] = dup2(bA.y); b[2] = dup2(bA.z); b[3] = dup2(bA.w);
            b[4] = dup2(bB.x); b[5] = dup2(bB.y); b[6] = dup2(bB.z); b[7] = dup2(bB.w);
            unsigned long long qp[4] = {qpA.x, qpA.y, qpB.x, qpB.y};
            #pragma unroll
            for (int i = 0; i < 4; ++i)
                #pragma unroll
                for (int j = 0; j < 8; ++j)
                    ffma2(acc[i][j], qp[i], b[j]);
            if (c + 1 < CH) {
                qpA = nqA; qpB = nqB; bA = nbA; bB = nbB;
            }
        }
        __syncthreads();
        buf ^= 1;
    }

    // epilogue: scatter rows (q pre-scaled by 1/T, so no extra scaling)
    #pragma unroll
    for (int i = 0; i < 4; ++i) {
        int rA = r0 + 2 * i, rB = rA + 1;
        int nA = rowidx[rA], nB = rowidx[rB];
        #pragma unroll
        for (int j = 0; j < 8; ++j) {
            float2 f = unpk(acc[i][j]);
            int col = (j < 4) ? (c4 + j) : (c4 + 64 + j - 4);
            size_t o = (size_t)(1 + k0 + col);
            if (nA >= 0) out[(size_t)nA * (KNEG + 1) + o] = f.x;
            if (nB >= 0) out[(size_t)nB * (KNEG + 1) + o] = f.y;
        }
    }
}

// ---------------------------------------------------------------- launch
extern "C" void kernel_launch(void* const* d_in, const int* in_sizes, int n_in,
                              void* d_out, int out_size) {
    const float* im_q   = (const float*)d_in[0];
    const float* im_k   = (const float*)d_in[1];
    const float* W_q    = (const float*)d_in[2];
    const float* W_k    = (const float*)d_in[3];
    const float* queues = (const float*)d_in[4];
    const int*   label  = (const int*)d_in[5];
    float* out = (float*)d_out;

    const int smem3 = (DIM * QS_LD + 2 * CH * 128) * 4 + 128 * 4;
    cudaFuncSetAttribute(lneg_kernel, cudaFuncAttributeMaxDynamicSharedMemorySize, smem3);

    init_kernel<<<1, 256>>>(out, (long long)out_size);
    proj_kernel<<<dim3(32, 4, 2), 256>>>(im_q, im_k, W_q, W_k);
    norm_kernel<<<N_ROWS, 128>>>(label, out);
    lneg_kernel<<<dim3(KNEG / 128, NG, 4), 256, smem3>>>(queues, out);
}

// round 7
// speedup vs baseline: 2.0332x; 1.6509x over previous
#include <cuda_runtime.h>
#include <cuda_bf16.h>
#include <cstdint>

#define INV_T   (1.0f/0.07f)
#define N_ROWS  512
#define D_IN    2048
#define DIM     128
#define KNEG    65536
#define NG      4
#define KT      2            // k-tiles (128 cols) per CTA

// ================= persistent device scratch =================
__device__ float g_part[8 * N_ROWS * DIM];
__device__ float g_q[N_ROWS * DIM];          // normalized q, pre-scaled 1/T
__device__ int   g_rows[NG * N_ROWS];
__device__ int   g_cnt[NG];

// ================= init =================
__global__ void init_kernel(float* __restrict__ out, long long out_size) {
    int t = threadIdx.x;
    if (t < NG) g_cnt[t] = 0;
    long long base = (long long)N_ROWS * (KNEG + 1);
    for (long long i = base + t; i < out_size; i += blockDim.x)
        out[i] = 0.0f;
}

// ================= projections (split-K partials) =================
__global__ void __launch_bounds__(256) proj_kernel(
    const float* __restrict__ im_q, const float* __restrict__ im_k,
    const float* __restrict__ W_q,  const float* __restrict__ W_k) {
    const int z  = blockIdx.z;
    const int ks = blockIdx.y;
    const int n0 = blockIdx.x * 16;
    const float* __restrict__ A = z ? im_k : im_q;
    const float* __restrict__ W = z ? W_k  : W_q;

    __shared__ float As[16][32];
    __shared__ float Bs[32][128];

    float acc[2][4] = {{0.f,0.f,0.f,0.f},{0.f,0.f,0.f,0.f}};
    const int t  = threadIdx.x;
    const int r0 = (t >> 5) << 1;
    const int c0 = (t & 31) << 2;
    const int kbeg = ks * 512;

    for (int kb = 0; kb < 512; kb += 32) {
        const int kbase = kbeg + kb;
        {
            int idx = t;
            #pragma unroll
            for (int i = 0; i < 2; ++i) {
                int r = idx >> 5, c = idx & 31;
                As[r][c] = A[(size_t)(n0 + r) * D_IN + kbase + c];
                idx += 256;
            }
        }
        #pragma unroll
        for (int i = 0; i < 16; ++i) {
            int idx = t + i * 256;
            int r = idx >> 7, c = idx & 127;
            Bs[r][c] = W[(size_t)(kbase + r) * DIM + c];
        }
        __syncthreads();
        #pragma unroll
        for (int kc = 0; kc < 32; ++kc) {
            float a0 = As[r0][kc], a1 = As[r0 + 1][kc];
            float4 b = *(const float4*)&Bs[kc][c0];
            acc[0][0] += a0 * b.x; acc[0][1] += a0 * b.y;
            acc[0][2] += a0 * b.z; acc[0][3] += a0 * b.w;
            acc[1][0] += a1 * b.x; acc[1][1] += a1 * b.y;
            acc[1][2] += a1 * b.z; acc[1][3] += a1 * b.w;
        }
        __syncthreads();
    }
    float* P = g_part + ((size_t)(z * 4 + ks) * N_ROWS + n0) * DIM;
    #pragma unroll
    for (int rr = 0; rr < 2; ++rr)
        #pragma unroll
        for (int cc = 0; cc < 4; ++cc)
            P[(size_t)(r0 + rr) * DIM + c0 + cc] = acc[rr][cc];
}

// ================= norm + l_pos + routing =================
__device__ __forceinline__ float block_reduce_128(float v, volatile float* sbuf) {
    #pragma unroll
    for (int o = 16; o > 0; o >>= 1)
        v += __shfl_xor_sync(0xffffffffu, v, o);
    __syncthreads();
    if ((threadIdx.x & 31) == 0) sbuf[threadIdx.x >> 5] = v;
    __syncthreads();
    return sbuf[0] + sbuf[1] + sbuf[2] + sbuf[3];
}

__global__ void __launch_bounds__(128) norm_kernel(const int* __restrict__ label,
                                                   float* __restrict__ out) {
    const int n = blockIdx.x;
    const int j = threadIdx.x;
    __shared__ float sbuf[4];

    float qv = 0.f, kv = 0.f;
    #pragma unroll
    for (int s = 0; s < 4; ++s) {
        qv += g_part[((size_t)s       * N_ROWS + n) * DIM + j];
        kv += g_part[((size_t)(4 + s) * N_ROWS + n) * DIM + j];
    }
    float sq = block_reduce_128(qv * qv, sbuf);
    float sk = block_reduce_128(kv * kv, sbuf);
    float qn = qv / fmaxf(sqrtf(sq), 1e-12f);
    float kn = kv / fmaxf(sqrtf(sk), 1e-12f);
    float lp = block_reduce_128(qn * kn, sbuf);

    g_q[(size_t)n * DIM + j] = qn * INV_T;

    if (j == 0) {
        out[(size_t)n * (KNEG + 1)] = lp * INV_T;
        int lab = label[n];
        int gq = ((lab - 1) % NG + NG) % NG;
        int p = atomicAdd(&g_cnt[gq], 1);
        g_rows[gq * N_ROWS + p] = n;
    }
}

// ================= l_neg: mma.sync bf16 hi/lo split =================
// SMEM (bytes):
#define OFF_ROWIDX 0
#define OFF_AHI    1024
#define OFF_ALO    (OFF_AHI + 34816)     // 35840
#define OFF_BHI    (OFF_ALO + 34816)     // 70656
#define OFF_BLO    (OFF_BHI + 34816)     // 105472
#define OFF_BST    (OFF_BLO + 34816)     // 140288  (fp32 stage 128x132)
#define SMEM_LNEG  (OFF_BST + 128*528)   // 207872
#define PAB        272                    // bf16 tile pitch in bytes (136 elems)
#define PST        528                    // fp32 stage pitch in bytes (132 elems)

__device__ __forceinline__ uint32_t smem_u32(const void* p) {
    uint32_t a;
    asm("{ .reg .u64 t; cvta.to.shared.u64 t, %1; cvt.u32.u64 %0, t; }" : "=r"(a) : "l"(p));
    return a;
}
__device__ __forceinline__ void bsplit2(float x0, float x1, uint32_t& h, uint32_t& l) {
    __nv_bfloat16 h0 = __float2bfloat16(x0), h1 = __float2bfloat16(x1);
    float r0 = x0 - __bfloat162float(h0);
    float r1 = x1 - __bfloat162float(h1);
    __nv_bfloat162 hp = __halves2bfloat162(h0, h1);
    __nv_bfloat162 lp = __halves2bfloat162(__float2bfloat16(r0), __float2bfloat16(r1));
    h = *(uint32_t*)&hp;
    l = *(uint32_t*)&lp;
}
__device__ __forceinline__ void ldmx4(uint32_t* r, uint32_t addr) {
    asm volatile("ldmatrix.sync.aligned.m8n8.x4.shared.b16 {%0,%1,%2,%3}, [%4];"
        : "=r"(r[0]),"=r"(r[1]),"=r"(r[2]),"=r"(r[3]) : "r"(addr));
}
__device__ __forceinline__ void ldmx4t(uint32_t* r, uint32_t addr) {
    asm volatile("ldmatrix.sync.aligned.m8n8.x4.trans.shared.b16 {%0,%1,%2,%3}, [%4];"
        : "=r"(r[0]),"=r"(r[1]),"=r"(r[2]),"=r"(r[3]) : "r"(addr));
}
__device__ __forceinline__ void mma16816(float* c, const uint32_t* a, const uint32_t* b) {
    asm volatile("mma.sync.aligned.m16n8k16.row.col.f32.bf16.bf16.f32 "
        "{%0,%1,%2,%3}, {%4,%5,%6,%7}, {%8,%9}, {%0,%1,%2,%3};"
        : "+f"(c[0]),"+f"(c[1]),"+f"(c[2]),"+f"(c[3])
        : "r"(a[0]),"r"(a[1]),"r"(a[2]),"r"(a[3]), "r"(b[0]),"r"(b[1]));
}
__device__ __forceinline__ void cpasync16(uint32_t dst, const void* src) {
    asm volatile("cp.async.cg.shared.global [%0], [%1], 16;" :: "r"(dst), "l"(src));
}

__global__ void __launch_bounds__(256) lneg_kernel(const float* __restrict__ queues,
                                                   float* __restrict__ out) {
    const int g   = blockIdx.y;
    const int m0  = blockIdx.z * 128;
    const int cnt = g_cnt[g];
    if (m0 >= cnt) return;

    extern __shared__ char smem[];
    const uint32_t sbase = smem_u32(smem);
    int* rowidx = (int*)(smem + OFF_ROWIDX);

    const int tid  = threadIdx.x;
    const int w    = tid >> 5;
    const int lane = tid & 31;
    const float* qgrp = queues + (size_t)g * DIM * KNEG;

    // rowidx
    int myrow = -1;
    if (tid < 128) {
        int r = m0 + tid;
        myrow = (r < cnt) ? g_rows[g * N_ROWS + r] : -1;
        rowidx[tid] = myrow;
    }

    // prefetch B stage for tile 0 (raw fp32, coalesced)
    {
        const int k0 = blockIdx.x * KT * 128;
        #pragma unroll
        for (int i = 0; i < 16; ++i) {
            int m = tid + (i << 8);
            int c = m >> 5, seg = m & 31;
            cpasync16(sbase + OFF_BST + (uint32_t)(c * PST + seg * 16),
                      qgrp + (size_t)c * KNEG + k0 + seg * 4);
        }
        asm volatile("cp.async.commit_group;");
    }

    // A prep: gather + hi/lo split into SMEM (threads 0..127, one row each)
    if (tid < 128) {
        char* arow_h = smem + OFF_AHI + tid * PAB;
        char* arow_l = smem + OFF_ALO + tid * PAB;
        if (myrow >= 0) {
            const float4* src = (const float4*)(g_q + (size_t)myrow * DIM);
            #pragma unroll
            for (int i = 0; i < 32; ++i) {
                float4 v = src[i];
                uint32_t hA, lA, hB, lB;
                bsplit2(v.x, v.y, hA, lA);
                bsplit2(v.z, v.w, hB, lB);
                *(uint2*)(arow_h + i * 8) = make_uint2(hA, hB);
                *(uint2*)(arow_l + i * 8) = make_uint2(lA, lB);
            }
        } else {
            #pragma unroll
            for (int i = 0; i < 32; ++i) {
                *(uint2*)(arow_h + i * 8) = make_uint2(0u, 0u);
                *(uint2*)(arow_l + i * 8) = make_uint2(0u, 0u);
            }
        }
    }

    const int  m_base   = (w >> 1) * 32;           // warp's 32 rows
    const int  n_basew  = (w & 1) * 64;            // warp's 64 cols
    const bool active   = (m0 + m_base) < cnt;

    for (int kt = 0; kt < KT; ++kt) {
        const int k0 = (blockIdx.x * KT + kt) * 128;

        asm volatile("cp.async.wait_group 0;");
        __syncthreads();   // stage ready; prior tile's SMEM reads done

        // convert fp32 stage -> bf16 hi/lo [c][n] tiles
        #pragma unroll
        for (int i = 0; i < 16; ++i) {
            int c = w + (i << 3);
            float4 v = *(const float4*)(smem + OFF_BST + c * PST + lane * 16);
            uint32_t hA, lA, hB, lB;
            bsplit2(v.x, v.y, hA, lA);
            bsplit2(v.z, v.w, hB, lB);
            *(uint2*)(smem + OFF_BHI + c * PAB + lane * 8) = make_uint2(hA, hB);
            *(uint2*)(smem + OFF_BLO + c * PAB + lane * 8) = make_uint2(lA, lB);
        }
        __syncthreads();

        // prefetch next tile's stage (overlaps MMA)
        if (kt + 1 < KT) {
            const int k0n = k0 + 128;
            #pragma unroll
            for (int i = 0; i < 16; ++i) {
                int m = tid + (i << 8);
                int c = m >> 5, seg = m & 31;
                cpasync16(sbase + OFF_BST + (uint32_t)(c * PST + seg * 16),
                          qgrp + (size_t)c * KNEG + k0n + seg * 4);
            }
            asm volatile("cp.async.commit_group;");
        }

        if (active) {
            float acc[2][8][4];
            #pragma unroll
            for (int mi = 0; mi < 2; ++mi)
                #pragma unroll
                for (int ni = 0; ni < 8; ++ni)
                    #pragma unroll
                    for (int e = 0; e < 4; ++e) acc[mi][ni][e] = 0.f;

            #pragma unroll
            for (int kf = 0; kf < 8; ++kf) {
                // A fragments (hi, lo) for 2 m-frags
                uint32_t ah[2][4], al[2][4];
                const uint32_t arow = (uint32_t)(m_base + (lane & 15));
                const uint32_t acol = (uint32_t)(kf * 32 + ((lane >> 4) << 4));
                #pragma unroll
                for (int mi = 0; mi < 2; ++mi) {
                    uint32_t ao = (arow + mi * 16) * PAB + acol;
                    ldmx4(ah[mi], sbase + OFF_AHI + ao);
                    ldmx4(al[mi], sbase + OFF_ALO + ao);
                }
                const uint32_t brow = (uint32_t)(kf * 16 + (lane & 15)) * PAB;
                #pragma unroll
                for (int np = 0; np < 4; ++np) {      // n-frag pairs (2 x n8)
                    uint32_t bcol = (uint32_t)(n_basew + np * 16 + ((lane >> 4) << 3)) * 2;
                    uint32_t bh[4], bl[4];
                    ldmx4t(bh, sbase + OFF_BHI + brow + bcol);
                    ldmx4t(bl, sbase + OFF_BLO + brow + bcol);
                    #pragma unroll
                    for (int mi = 0; mi < 2; ++mi) {
                        mma16816(acc[mi][2*np],   ah[mi], bh);
                        mma16816(acc[mi][2*np],   ah[mi], bl);
                        mma16816(acc[mi][2*np],   al[mi], bh);
                        mma16816(acc[mi][2*np+1], ah[mi], bh + 2);
                        mma16816(acc[mi][2*np+1], ah[mi], bl + 2);
                        mma16816(acc[mi][2*np+1], al[mi], bh + 2);
                    }
                }
            }

            // epilogue: scalar STG.32 (output col base is odd: 1 + k0 + ...)
            #pragma unroll
            for (int mi = 0; mi < 2; ++mi) {
                int r0 = m_base + mi * 16 + (lane >> 2);
                int n0r = rowidx[r0];
                int n1r = rowidx[r0 + 8];
                #pragma unroll
                for (int ni = 0; ni < 8; ++ni) {
                    size_t col = (size_t)(1 + k0 + n_basew + ni * 8 + (lane & 3) * 2);
                    if (n0r >= 0) {
                        float* p0 = out + (size_t)n0r * (KNEG + 1) + col;
                        p0[0] = acc[mi][ni][0];
                        p0[1] = acc[mi][ni][1];
                    }
                    if (n1r >= 0) {
                        float* p1 = out + (size_t)n1r * (KNEG + 1) + col;
                        p1[0] = acc[mi][ni][2];
                        p1[1] = acc[mi][ni][3];
                    }
                }
            }
        }
        __syncthreads();   // all B reads done before next conversion overwrites
    }
}

// ================= launch =================
extern "C" void kernel_launch(void* const* d_in, const int* in_sizes, int n_in,
                              void* d_out, int out_size) {
    const float* im_q   = (const float*)d_in[0];
    const float* im_k   = (const float*)d_in[1];
    const float* W_q    = (const float*)d_in[2];
    const float* W_k    = (const float*)d_in[3];
    const float* queues = (const float*)d_in[4];
    const int*   label  = (const int*)d_in[5];
    float* out = (float*)d_out;

    cudaFuncSetAttribute(lneg_kernel, cudaFuncAttributeMaxDynamicSharedMemorySize, SMEM_LNEG);

    init_kernel<<<1, 256>>>(out, (long long)out_size);
    proj_kernel<<<dim3(32, 4, 2), 256>>>(im_q, im_k, W_q, W_k);
    norm_kernel<<<N_ROWS, 128>>>(label, out);
    lneg_kernel<<<dim3(KNEG / (128 * KT), NG, 4), 256, SMEM_LNEG>>>(queues, out);
}

// round 8
// speedup vs baseline: 2.6421x; 1.2995x over previous
#include <cuda_runtime.h>
#include <cuda_bf16.h>
#include <cstdint>

#define INV_T   (1.0f/0.07f)
#define N_ROWS  512
#define D_IN    2048
#define DIM     128
#define KNEG    65536
#define NG      4
#define KT      4            // k-tiles (128 cols) per CTA

// ================= persistent device scratch =================
__device__ float g_part[8 * N_ROWS * DIM];
__device__ float g_q[N_ROWS * DIM];          // normalized q * 1/T, tf32-rounded
__device__ int   g_rows[NG * N_ROWS];
__device__ int   g_cnt[NG];

// ================= init =================
__global__ void init_kernel(float* __restrict__ out, long long out_size) {
    int t = threadIdx.x;
    if (t < NG) g_cnt[t] = 0;
    long long base = (long long)N_ROWS * (KNEG + 1);
    for (long long i = base + t; i < out_size; i += blockDim.x)
        out[i] = 0.0f;
}

// ================= projections (split-K partials) =================
__global__ void __launch_bounds__(256) proj_kernel(
    const float* __restrict__ im_q, const float* __restrict__ im_k,
    const float* __restrict__ W_q,  const float* __restrict__ W_k) {
    const int z  = blockIdx.z;
    const int ks = blockIdx.y;
    const int n0 = blockIdx.x * 16;
    const float* __restrict__ A = z ? im_k : im_q;
    const float* __restrict__ W = z ? W_k  : W_q;

    __shared__ float As[16][32];
    __shared__ float Bs[32][128];

    float acc[2][4] = {{0.f,0.f,0.f,0.f},{0.f,0.f,0.f,0.f}};
    const int t  = threadIdx.x;
    const int r0 = (t >> 5) << 1;
    const int c0 = (t & 31) << 2;
    const int kbeg = ks * 512;

    for (int kb = 0; kb < 512; kb += 32) {
        const int kbase = kbeg + kb;
        {
            int idx = t;
            #pragma unroll
            for (int i = 0; i < 2; ++i) {
                int r = idx >> 5, c = idx & 31;
                As[r][c] = A[(size_t)(n0 + r) * D_IN + kbase + c];
                idx += 256;
            }
        }
        #pragma unroll
        for (int i = 0; i < 16; ++i) {
            int idx = t + i * 256;
            int r = idx >> 7, c = idx & 127;
            Bs[r][c] = W[(size_t)(kbase + r) * DIM + c];
        }
        __syncthreads();
        #pragma unroll
        for (int kc = 0; kc < 32; ++kc) {
            float a0 = As[r0][kc], a1 = As[r0 + 1][kc];
            float4 b = *(const float4*)&Bs[kc][c0];
            acc[0][0] += a0 * b.x; acc[0][1] += a0 * b.y;
            acc[0][2] += a0 * b.z; acc[0][3] += a0 * b.w;
            acc[1][0] += a1 * b.x; acc[1][1] += a1 * b.y;
            acc[1][2] += a1 * b.z; acc[1][3] += a1 * b.w;
        }
        __syncthreads();
    }
    float* P = g_part + ((size_t)(z * 4 + ks) * N_ROWS + n0) * DIM;
    #pragma unroll
    for (int rr = 0; rr < 2; ++rr)
        #pragma unroll
        for (int cc = 0; cc < 4; ++cc)
            P[(size_t)(r0 + rr) * DIM + c0 + cc] = acc[rr][cc];
}

// ================= norm + l_pos + routing =================
__device__ __forceinline__ float block_reduce_128(float v, volatile float* sbuf) {
    #pragma unroll
    for (int o = 16; o > 0; o >>= 1)
        v += __shfl_xor_sync(0xffffffffu, v, o);
    __syncthreads();
    if ((threadIdx.x & 31) == 0) sbuf[threadIdx.x >> 5] = v;
    __syncthreads();
    return sbuf[0] + sbuf[1] + sbuf[2] + sbuf[3];
}

__global__ void __launch_bounds__(128) norm_kernel(const int* __restrict__ label,
                                                   float* __restrict__ out) {
    const int n = blockIdx.x;
    const int j = threadIdx.x;
    __shared__ float sbuf[4];

    float qv = 0.f, kv = 0.f;
    #pragma unroll
    for (int s = 0; s < 4; ++s) {
        qv += g_part[((size_t)s       * N_ROWS + n) * DIM + j];
        kv += g_part[((size_t)(4 + s) * N_ROWS + n) * DIM + j];
    }
    float sq = block_reduce_128(qv * qv, sbuf);
    float sk = block_reduce_128(kv * kv, sbuf);
    float qn = qv / fmaxf(sqrtf(sq), 1e-12f);
    float kn = kv / fmaxf(sqrtf(sk), 1e-12f);
    float lp = block_reduce_128(qn * kn, sbuf);

    // store q * 1/T rounded to tf32 (round-to-nearest) for the MMA
    float qscaled = qn * INV_T;
    uint32_t qt;
    asm("cvt.rna.tf32.f32 %0, %1;" : "=r"(qt) : "f"(qscaled));
    g_q[(size_t)n * DIM + j] = __uint_as_float(qt);

    if (j == 0) {
        out[(size_t)n * (KNEG + 1)] = lp * INV_T;
        int lab = label[n];
        int gq = ((lab - 1) % NG + NG) % NG;
        int p = atomicAdd(&g_cnt[gq], 1);
        g_rows[gq * N_ROWS + p] = n;
    }
}

// ================= l_neg: single-pass tf32 mma.sync =================
// SMEM layout (bytes):
//   [0..512)      rowidx (128 int)
//   [1024..68608)       A  : 128 rows x 132 floats (PA=132 -> frag LDS conflict-free)
//   [68608..207872)     B  : 2 buffers x 128 c-rows x 136 floats (PB=136 -> conflict-free)
#define OFF_ROWIDX 0
#define OFF_A      1024
#define PA         132
#define OFF_B      (OFF_A + 128 * PA * 4)          // 68608
#define PB         136
#define B_BUF_BYTES (128 * PB * 4)                 // 69632
#define SMEM_LNEG  (OFF_B + 2 * B_BUF_BYTES)       // 207872

__device__ __forceinline__ uint32_t smem_u32(const void* p) {
    uint32_t a;
    asm("{ .reg .u64 t; cvta.to.shared.u64 t, %1; cvt.u32.u64 %0, t; }" : "=r"(a) : "l"(p));
    return a;
}
__device__ __forceinline__ void cpasync16(uint32_t dst, const void* src) {
    asm volatile("cp.async.cg.shared.global [%0], [%1], 16;" :: "r"(dst), "l"(src));
}
__device__ __forceinline__ void mma_tf32(float* c, const uint32_t* a, const uint32_t* b) {
    asm volatile("mma.sync.aligned.m16n8k8.row.col.f32.tf32.tf32.f32 "
        "{%0,%1,%2,%3}, {%4,%5,%6,%7}, {%8,%9}, {%0,%1,%2,%3};"
        : "+f"(c[0]),"+f"(c[1]),"+f"(c[2]),"+f"(c[3])
        : "r"(a[0]),"r"(a[1]),"r"(a[2]),"r"(a[3]), "r"(b[0]),"r"(b[1]));
}

__global__ void __launch_bounds__(256) lneg_kernel(const float* __restrict__ queues,
                                                   float* __restrict__ out) {
    const int g   = blockIdx.y;
    const int m0  = blockIdx.z * 128;
    const int cnt = g_cnt[g];
    if (m0 >= cnt) return;

    extern __shared__ char smem[];
    const uint32_t sbase = smem_u32(smem);
    int* rowidx = (int*)(smem + OFF_ROWIDX);
    float* As   = (float*)(smem + OFF_A);

    const int tid  = threadIdx.x;
    const int w    = tid >> 5;
    const int lane = tid & 31;
    const float* qgrp = queues + (size_t)g * DIM * KNEG;
    const int kbase_cta = blockIdx.x * KT * 128;

    // prefetch B tile 0 into buffer 0 (raw fp32, coalesced; tf32 uses high bits)
    {
        #pragma unroll
        for (int i = 0; i < 16; ++i) {
            int m = tid + (i << 8);
            int c = m >> 5, seg = m & 31;
            cpasync16(sbase + OFF_B + (uint32_t)(c * (PB * 4) + seg * 16),
                      qgrp + (size_t)c * KNEG + kbase_cta + seg * 4);
        }
        asm volatile("cp.async.commit_group;");
    }

    // rowidx + A fill (threads 0..127, one gathered q row each)
    if (tid < 128) {
        int r = m0 + tid;
        int myrow = (r < cnt) ? g_rows[g * N_ROWS + r] : -1;
        rowidx[tid] = myrow;
        float* arow = As + tid * PA;
        if (myrow >= 0) {
            const float4* src = (const float4*)(g_q + (size_t)myrow * DIM);
            #pragma unroll
            for (int i = 0; i < 32; ++i)
                *(float4*)(arow + i * 4) = src[i];
        } else {
            #pragma unroll
            for (int i = 0; i < 32; ++i)
                *(float4*)(arow + i * 4) = make_float4(0.f, 0.f, 0.f, 0.f);
        }
    }

    const int  m_base  = (w >> 1) * 32;    // warp's 32 rows
    const int  n_basew = (w & 1) * 64;     // warp's 64 cols
    const bool active  = (m0 + m_base) < cnt;

    for (int kt = 0; kt < KT; ++kt) {
        const int k0 = kbase_cta + kt * 128;
        const float* Bs = (const float*)(smem + OFF_B + (kt & 1) * B_BUF_BYTES);

        asm volatile("cp.async.wait_group 0;");
        __syncthreads();   // buffer(kt) ready; all warps done reading buffer(kt-1)

        // prefetch next tile into the other buffer (overlaps MMA below)
        if (kt + 1 < KT) {
            uint32_t dstb = sbase + OFF_B + ((kt + 1) & 1) * B_BUF_BYTES;
            const float* srcb = qgrp + k0 + 128;
            #pragma unroll
            for (int i = 0; i < 16; ++i) {
                int m = tid + (i << 8);
                int c = m >> 5, seg = m & 31;
                cpasync16(dstb + (uint32_t)(c * (PB * 4) + seg * 16),
                          srcb + (size_t)c * KNEG + seg * 4);
            }
            asm volatile("cp.async.commit_group;");
        }

        if (active) {
            float acc[2][8][4];
            #pragma unroll
            for (int mi = 0; mi < 2; ++mi)
                #pragma unroll
                for (int ni = 0; ni < 8; ++ni)
                    #pragma unroll
                    for (int e = 0; e < 4; ++e) acc[mi][ni][e] = 0.f;

            const int arow0 = m_base + (lane >> 2);
            const int acol0 = lane & 3;
            const int bn0   = n_basew + (lane >> 2);
            const int bk0   = lane & 3;

            #pragma unroll
            for (int ks = 0; ks < 16; ++ks) {
                const int k = ks * 8;
                uint32_t a[2][4];
                #pragma unroll
                for (int mi = 0; mi < 2; ++mi) {
                    const float* ap = As + (arow0 + mi * 16) * PA + (k + acol0);
                    a[mi][0] = __float_as_uint(ap[0]);
                    a[mi][1] = __float_as_uint(ap[8 * PA]);
                    a[mi][2] = __float_as_uint(ap[4]);
                    a[mi][3] = __float_as_uint(ap[8 * PA + 4]);
                }
                #pragma unroll
                for (int ni = 0; ni < 8; ++ni) {
                    const float* bp = Bs + (size_t)(k + bk0) * PB + bn0 + ni * 8;
                    uint32_t b[2];
                    b[0] = __float_as_uint(bp[0]);
                    b[1] = __float_as_uint(bp[4 * PB]);
                    mma_tf32(acc[0][ni], a[0], b);
                    mma_tf32(acc[1][ni], a[1], b);
                }
            }

            // epilogue: scalar stores (col base 1 + k0 is odd)
            #pragma unroll
            for (int mi = 0; mi < 2; ++mi) {
                int rlo = m_base + mi * 16 + (lane >> 2);
                int n0r = rowidx[rlo];
                int n1r = rowidx[rlo + 8];
                #pragma unroll
                for (int ni = 0; ni < 8; ++ni) {
                    size_t col = (size_t)(1 + k0 + n_basew + ni * 8 + (lane & 3) * 2);
                    if (n0r >= 0) {
                        float* p0 = out + (size_t)n0r * (KNEG + 1) + col;
                        p0[0] = acc[mi][ni][0];
                        p0[1] = acc[mi][ni][1];
                    }
                    if (n1r >= 0) {
                        float* p1 = out + (size_t)n1r * (KNEG + 1) + col;
                        p1[0] = acc[mi][ni][2];
                        p1[1] = acc[mi][ni][3];
                    }
                }
            }
        }
    }
}

// ================= launch =================
extern "C" void kernel_launch(void* const* d_in, const int* in_sizes, int n_in,
                              void* d_out, int out_size) {
    const float* im_q   = (const float*)d_in[0];
    const float* im_k   = (const float*)d_in[1];
    const float* W_q    = (const float*)d_in[2];
    const float* W_k    = (const float*)d_in[3];
    const float* queues = (const float*)d_in[4];
    const int*   label  = (const int*)d_in[5];
    float* out = (float*)d_out;

    cudaFuncSetAttribute(lneg_kernel, cudaFuncAttributeMaxDynamicSharedMemorySize, SMEM_LNEG);

    init_kernel<<<1, 256>>>(out, (long long)out_size);
    proj_kernel<<<dim3(32, 4, 2), 256>>>(im_q, im_k, W_q, W_k);
    norm_kernel<<<N_ROWS, 128>>>(label, out);
    lneg_kernel<<<dim3(KNEG / (128 * KT), NG, 4), 256, SMEM_LNEG>>>(queues, out);
}